// round 12
// baseline (speedup 1.0000x reference)
#include <cuda_runtime.h>

#define T_LEN 4096
#define D_DIM 1024
#define NCTA  128
#define CPC   8      // columns per CTA (= warps per CTA)
#define NREP  32     // replica rows (one per lane)

typedef unsigned long long ull;

// ---------------- scratch (device globals: no allocation allowed) -----------
__device__ float  g_Gr[T_LEN * D_DIM];
__device__ float  g_Gz[T_LEN * D_DIM];
__device__ float  g_Gn[T_LEN * D_DIM];
__device__ float  g_h [T_LEN * D_DIM];            // plain h history (post GEMM)
__device__ float2 g_ring[2 * NREP * D_DIM];       // {h, tag} ring, 2 slots x 32 replicas

// ---------------- PTX helpers ----------------------------------------------
__device__ __forceinline__ ull pack2(float lo, float hi) {
    ull r;
    asm("mov.b64 %0, {%1, %2};" : "=l"(r) : "f"(lo), "f"(hi));
    return r;
}
__device__ __forceinline__ void unpack2(ull v, float& lo, float& hi) {
    asm("mov.b64 {%0, %1}, %2;" : "=f"(lo), "=f"(hi) : "l"(v));
}
__device__ __forceinline__ void fma2(ull& d, ull a, ull b) {
    asm("fma.rn.f32x2 %0, %1, %2, %0;" : "+l"(d) : "l"(a), "l"(b));
}
__device__ __forceinline__ float4 ldvol_f4(const float4* p) {
    float4 v;
    asm volatile("ld.volatile.global.v4.f32 {%0,%1,%2,%3}, [%4];"
                 : "=f"(v.x), "=f"(v.y), "=f"(v.z), "=f"(v.w) : "l"(p));
    return v;
}
__device__ __forceinline__ void stvol_f2(float2* p, float a, float b) {
    asm volatile("st.volatile.global.v2.f32 [%0], {%1,%2};" :: "l"(p), "f"(a), "f"(b));
}

// ---------------- ring clear (fresh each graph replay) ----------------------
__global__ void clear_ring_kernel() {
    int i = blockIdx.x * blockDim.x + threadIdx.x;   // float4 index
    ((float4*)g_ring)[i] = make_float4(0.f, 0.f, 0.f, 0.f);
}

// ---------------- fp32 GEMM: C = (relu?)(A) @ B + bias, 128x128 / 8x8 ------
template <bool RELU_A>
__global__ void __launch_bounds__(256) gemm128_kernel(
    const float* __restrict__ A, const float* __restrict__ B,
    const float* __restrict__ bias, float* __restrict__ C,
    int M, int N, int K)
{
    __shared__ float As[8][128];   // As[k][m] (transposed)
    __shared__ float Bs[8][128];   // Bs[k][n]

    const int tid = threadIdx.x;
    const int bm = blockIdx.y << 7, bn = blockIdx.x << 7;

    const int arow = tid >> 1;             // 0..127
    const int acol = (tid & 1) << 2;       // 0 or 4
    const int brow = tid >> 5;             // 0..7
    const int bcol = (tid & 31) << 2;      // 0..124

    const float* Ap = A + (size_t)(bm + arow) * K + acol;
    const float* Bp = B + (size_t)brow * N + bn + bcol;

    const int tx = tid & 15, ty = tid >> 4;

    float acc[8][8];
#pragma unroll
    for (int i = 0; i < 8; i++)
#pragma unroll
        for (int j = 0; j < 8; j++) acc[i][j] = 0.f;

    float4 a4 = *(const float4*)Ap;
    float4 b4 = *(const float4*)Bp;

    for (int kb = 0; kb < K; kb += 8) {
        float4 av = a4, bv = b4;
        if (RELU_A) {
            av.x = fmaxf(av.x, 0.f); av.y = fmaxf(av.y, 0.f);
            av.z = fmaxf(av.z, 0.f); av.w = fmaxf(av.w, 0.f);
        }
        As[acol + 0][arow] = av.x;
        As[acol + 1][arow] = av.y;
        As[acol + 2][arow] = av.z;
        As[acol + 3][arow] = av.w;
        *(float4*)&Bs[brow][bcol] = bv;
        __syncthreads();

        if (kb + 8 < K) {                       // prefetch next k-slice
            a4 = *(const float4*)(Ap + kb + 8);
            b4 = *(const float4*)(Bp + (size_t)(kb + 8) * N);
        }

#pragma unroll
        for (int kk = 0; kk < 8; kk++) {
            float a8[8], b8[8];
            *(float4*)(a8)     = *(const float4*)&As[kk][ty << 3];
            *(float4*)(a8 + 4) = *(const float4*)&As[kk][(ty << 3) + 4];
            *(float4*)(b8)     = *(const float4*)&Bs[kk][tx << 3];
            *(float4*)(b8 + 4) = *(const float4*)&Bs[kk][(tx << 3) + 4];
#pragma unroll
            for (int i = 0; i < 8; i++)
#pragma unroll
                for (int j = 0; j < 8; j++)
                    acc[i][j] = fmaf(a8[i], b8[j], acc[i][j]);
        }
        __syncthreads();
    }

    float bb[8];
    *(float4*)(bb)     = *(const float4*)&bias[bn + (tx << 3)];
    *(float4*)(bb + 4) = *(const float4*)&bias[bn + (tx << 3) + 4];
#pragma unroll
    for (int i = 0; i < 8; i++) {
        float* Cp = C + (size_t)(bm + (ty << 3) + i) * N + bn + (tx << 3);
        *(float4*)(Cp)     = make_float4(acc[i][0] + bb[0], acc[i][1] + bb[1],
                                         acc[i][2] + bb[2], acc[i][3] + bb[3]);
        *(float4*)(Cp + 4) = make_float4(acc[i][4] + bb[4], acc[i][5] + bb[5],
                                         acc[i][6] + bb[6], acc[i][7] + bb[7]);
    }
}

// ---------------- persistent GRU recurrence ---------------------------------
// 128 CTAs x 256 threads. Warp w owns column cta*8+w; weights in registers.
// Transport: each producer warp broadcasts h to 32 replica rows (one per
// lane); each consumer CTA polls ONLY its own replica (4 pollers/slot).
// Detect and data arrival are the same RTT; no counters, no fences.
__global__ void __launch_bounds__(256, 1) gru_recurrence_kernel(
    const float* __restrict__ Whr, const float* __restrict__ Whz,
    const float* __restrict__ Whn, const float* __restrict__ bhn,
    const float* __restrict__ init_state)
{
    __shared__ float sh_h[2][D_DIM];       // double buffer: h rows

    const int tid  = threadIdx.x;
    const int warp = tid >> 5, lane = tid & 31;
    const int col  = blockIdx.x * CPC + warp;
    const int rep  = blockIdx.x & (NREP - 1);   // this CTA's replica row

    // ---- one-time: weight slice into registers (48 packed f32x2 / gate) ----
    ull wr[16], wz[16], wn[16];
#pragma unroll
    for (int i = 0; i < 16; i++) {
        const int k0 = 2 * (lane + 32 * i);
        const size_t o0 = (size_t)k0 * D_DIM + col;
        const size_t o1 = (size_t)(k0 + 1) * D_DIM + col;
        wr[i] = pack2(Whr[o0], Whr[o1]);
        wz[i] = pack2(Whz[o0], Whz[o1]);
        wn[i] = pack2(Whn[o0], Whn[o1]);
    }
    const float bhn_c = bhn[col];

    float h_prev = init_state[col];
    float gr_c = g_Gr[col], gz_c = g_Gz[col], gn_c = g_Gn[col];

    const int s0 = tid, s1 = tid + 256;    // this thread's two float4 poll slots

    for (int t = 0; t < T_LEN; t++) {
        float* dst = sh_h[t & 1];

        // ---- prefetch next step's gate pre-activations (independent) ----
        float grn = 0.f, gzn = 0.f, gnn = 0.f;
        if (lane == 0 && t + 1 < T_LEN) {
            const size_t o = (size_t)(t + 1) * D_DIM + col;
            grn = __ldg(&g_Gr[o]); gzn = __ldg(&g_Gz[o]); gnn = __ldg(&g_Gn[o]);
        }

        // ---- stage h_{t-1}: dual-slot poll of OWN replica row ----
        if (t == 0) {
            float4 v = ((const float4*)init_state)[tid];
            *(float4*)&dst[tid << 2] = v;
        } else {
            const float4* src = (const float4*)
                (g_ring + ((size_t)(((t - 1) & 1) * NREP + rep)) * D_DIM);
            const unsigned tag = __float_as_uint((float)t);   // producer wrote t-1's h with tag t
            float4 a = ldvol_f4(src + s0);
            float4 b = ldvol_f4(src + s1);
            bool da = false, db = false;
            while (true) {
                if (!da && __float_as_uint(a.y) == tag && __float_as_uint(a.w) == tag) {
                    ((float2*)dst)[s0] = make_float2(a.x, a.z);
                    da = true;
                }
                if (!db && __float_as_uint(b.y) == tag && __float_as_uint(b.w) == tag) {
                    ((float2*)dst)[s1] = make_float2(b.x, b.z);
                    db = true;
                }
                if (da && db) break;
                if (!da) a = ldvol_f4(src + s0);
                if (!db) b = ldvol_f4(src + s1);
            }
        }
        __syncthreads();   // staging complete; double buffer handles WAR

        // ---- packed dot products (3 gates, 2 accumulators each) ----
        const ull* h2 = (const ull*)dst;
        ull ar0 = 0, ar1 = 0, az0 = 0, az1 = 0, an0 = 0, an1 = 0;
#pragma unroll
        for (int i = 0; i < 16; i += 2) {
            ull h0 = h2[lane + 32 * i];
            ull h1 = h2[lane + 32 * (i + 1)];
            fma2(ar0, h0, wr[i]);  fma2(ar1, h1, wr[i + 1]);
            fma2(az0, h0, wz[i]);  fma2(az1, h1, wz[i + 1]);
            fma2(an0, h0, wn[i]);  fma2(an1, h1, wn[i + 1]);
        }
        float lo, hi, ar, az, an;
        unpack2(ar0, lo, hi); ar = lo + hi; unpack2(ar1, lo, hi); ar += lo + hi;
        unpack2(az0, lo, hi); az = lo + hi; unpack2(az1, lo, hi); az += lo + hi;
        unpack2(an0, lo, hi); an = lo + hi; unpack2(an1, lo, hi); an += lo + hi;

#pragma unroll
        for (int o = 16; o > 0; o >>= 1) {
            ar += __shfl_xor_sync(0xFFFFFFFFu, ar, o);
            az += __shfl_xor_sync(0xFFFFFFFFu, az, o);
            an += __shfl_xor_sync(0xFFFFFFFFu, an, o);
        }

        // ---- gate math (lane 0), broadcast, 32-replica publish ----
        float hnew = 0.f;
        if (lane == 0) {
            float er = __expf(-(gr_c + ar));
            float r  = __fdividef(1.f, 1.f + er);
            float ez = __expf(-(gz_c + az));
            float z  = __fdividef(1.f, 1.f + ez);
            float nx = gn_c + r * (an + bhn_c);
            float en = __expf(-2.f * nx);
            float n  = __fdividef(1.f - en, 1.f + en);      // tanh(nx)
            hnew = n + z * (h_prev - n);
        }
        hnew = __shfl_sync(0xFFFFFFFFu, hnew, 0);
        // every lane stores {h, tag=t+1} into its replica row (slot t&1)
        stvol_f2(g_ring + ((size_t)((t & 1) * NREP + lane)) * D_DIM + col,
                 hnew, (float)(t + 1));
        if (lane == 0) {
            g_h[(size_t)t * D_DIM + col] = hnew;   // history for post-GEMM
            h_prev = hnew;
            gr_c = grn; gz_c = gzn; gn_c = gnn;
        }
        // no trailing bar: next step's staging bar gates sh_h reuse
    }
}

// ---------------- residual + layernorm (in-place on d_out) -----------------
__global__ void __launch_bounds__(256) layernorm_kernel(
    const float* __restrict__ xs, const float* __restrict__ ln_scale,
    const float* __restrict__ ln_bias, float* __restrict__ inout)
{
    __shared__ float red0[8], red1[8];
    const int t = blockIdx.x, tid = threadIdx.x;
    const float* xrow = xs + (size_t)t * D_DIM;
    float* yrow = inout + (size_t)t * D_DIM;

    float v[4];
    float s = 0.f, s2 = 0.f;
#pragma unroll
    for (int i = 0; i < 4; i++) {
        int idx = tid + i * 256;
        float y = xrow[idx] + yrow[idx];
        v[i] = y; s += y; s2 += y * y;
    }
#pragma unroll
    for (int o = 16; o > 0; o >>= 1) {
        s  += __shfl_xor_sync(0xFFFFFFFFu, s,  o);
        s2 += __shfl_xor_sync(0xFFFFFFFFu, s2, o);
    }
    const int warp = tid >> 5, lane = tid & 31;
    if (lane == 0) { red0[warp] = s; red1[warp] = s2; }
    __syncthreads();
    if (warp == 0) {
        float a = (lane < 8) ? red0[lane] : 0.f;
        float b = (lane < 8) ? red1[lane] : 0.f;
#pragma unroll
        for (int o = 4; o > 0; o >>= 1) {
            a += __shfl_xor_sync(0xFFFFFFFFu, a, o);
            b += __shfl_xor_sync(0xFFFFFFFFu, b, o);
        }
        if (lane == 0) { red0[0] = a; red1[0] = b; }
    }
    __syncthreads();

    const float mu   = red0[0] * (1.f / D_DIM);
    const float var  = red1[0] * (1.f / D_DIM) - mu * mu;
    const float rstd = rsqrtf(var + 1e-6f);
#pragma unroll
    for (int i = 0; i < 4; i++) {
        int idx = tid + i * 256;
        yrow[idx] = (v[i] - mu) * rstd * ln_scale[idx] + ln_bias[idx];
    }
}

// ---------------- launcher --------------------------------------------------
extern "C" void kernel_launch(void* const* d_in, const int* in_sizes, int n_in,
                              void* d_out, int out_size)
{
    const float* xs        = (const float*)d_in[0];
    const float* init_st   = (const float*)d_in[1];
    const float* Wir       = (const float*)d_in[2];
    const float* Wiz       = (const float*)d_in[3];
    const float* Win       = (const float*)d_in[4];
    const float* bir       = (const float*)d_in[5];
    const float* biz       = (const float*)d_in[6];
    const float* bin_      = (const float*)d_in[7];
    const float* Whr       = (const float*)d_in[8];
    const float* Whz       = (const float*)d_in[9];
    const float* Whn       = (const float*)d_in[10];
    const float* bhn       = (const float*)d_in[11];
    const float* Wl        = (const float*)d_in[12];
    const float* bl        = (const float*)d_in[13];
    const float* ln_scale  = (const float*)d_in[14];
    const float* ln_bias   = (const float*)d_in[15];
    float* out = (float*)d_out;

    void *pGr, *pGz, *pGn, *pH;
    cudaGetSymbolAddress(&pGr, g_Gr);
    cudaGetSymbolAddress(&pGz, g_Gz);
    cudaGetSymbolAddress(&pGn, g_Gn);
    cudaGetSymbolAddress(&pH,  g_h);

    dim3 gemm_grid(D_DIM / 128, T_LEN / 128);   // (8, 32)

    // 1) clear replica ring (graph-replay determinism): 512KB / 16B = 32K f4
    clear_ring_kernel<<<(2 * NREP * D_DIM * 2 / 4) / 256, 256>>>();

    // 2) input-side gate pre-GEMMs (parallel over time)
    gemm128_kernel<false><<<gemm_grid, 256>>>(xs, Wir, bir, (float*)pGr,
                                              T_LEN, D_DIM, D_DIM);
    gemm128_kernel<false><<<gemm_grid, 256>>>(xs, Wiz, biz, (float*)pGz,
                                              T_LEN, D_DIM, D_DIM);
    gemm128_kernel<false><<<gemm_grid, 256>>>(xs, Win, bin_, (float*)pGn,
                                              T_LEN, D_DIM, D_DIM);

    // 3) sequential recurrence: persistent grid, register-resident weights
    gru_recurrence_kernel<<<NCTA, 256>>>(Whr, Whz, Whn, bhn, init_st);

    // 4) post dense: d_out = relu(h) @ Wl + bl
    gemm128_kernel<true><<<gemm_grid, 256>>>((const float*)pH, Wl, bl, out,
                                             T_LEN, D_DIM, D_DIM);

    // 5) residual + layernorm in-place on d_out
    layernorm_kernel<<<T_LEN, 256>>>(xs, ln_scale, ln_bias, out);
}

// round 13
// speedup vs baseline: 1.3002x; 1.3002x over previous
#include <cuda_runtime.h>

#define T_LEN 4096
#define D_DIM 1024
#define NCTA  128
#define CPC   8      // columns per CTA (= warps per CTA)

typedef unsigned long long ull;

// ---------------- scratch (device globals: no allocation allowed) -----------
__device__ float    g_Gr[T_LEN * D_DIM];
__device__ float    g_Gz[T_LEN * D_DIM];
__device__ float    g_Gn[T_LEN * D_DIM];
__device__ float    g_h [T_LEN * D_DIM];   // plain h history
__device__ unsigned g_cnt[T_LEN];          // per-step arrival counter

// ---------------- PTX helpers ----------------------------------------------
__device__ __forceinline__ ull pack2(float lo, float hi) {
    ull r;
    asm("mov.b64 %0, {%1, %2};" : "=l"(r) : "f"(lo), "f"(hi));
    return r;
}
__device__ __forceinline__ void unpack2(ull v, float& lo, float& hi) {
    asm("mov.b64 {%0, %1}, %2;" : "=f"(lo), "=f"(hi) : "l"(v));
}
__device__ __forceinline__ void fma2(ull& d, ull a, ull b) {
    asm("fma.rn.f32x2 %0, %1, %2, %0;" : "+l"(d) : "l"(a), "l"(b));
}
__device__ __forceinline__ unsigned ld_acquire(const unsigned* p) {
    unsigned v;
    asm volatile("ld.acquire.gpu.u32 %0, [%1];" : "=r"(v) : "l"(p));
    return v;
}

// ---------------- counter clear (fresh each graph replay) -------------------
__global__ void clear_cnt_kernel() {
    int i = blockIdx.x * blockDim.x + threadIdx.x;
    if (i < T_LEN) g_cnt[i] = 0u;
}

// ---------------- fp32 GEMM body: C = (relu?)(A) @ B + bias, 128x128 / 8x8 --
template <bool RELU_A>
__device__ __forceinline__ void gemm128_body(
    const float* __restrict__ A, const float* __restrict__ B,
    const float* __restrict__ bias, float* __restrict__ C,
    int M, int N, int K)
{
    __shared__ float As[8][128];   // As[k][m] (transposed)
    __shared__ float Bs[8][128];   // Bs[k][n]

    const int tid = threadIdx.x;
    const int bm = blockIdx.y << 7, bn = blockIdx.x << 7;

    const int arow = tid >> 1;             // 0..127
    const int acol = (tid & 1) << 2;       // 0 or 4
    const int brow = tid >> 5;             // 0..7
    const int bcol = (tid & 31) << 2;      // 0..124

    const float* Ap = A + (size_t)(bm + arow) * K + acol;
    const float* Bp = B + (size_t)brow * N + bn + bcol;

    const int tx = tid & 15, ty = tid >> 4;

    float acc[8][8];
#pragma unroll
    for (int i = 0; i < 8; i++)
#pragma unroll
        for (int j = 0; j < 8; j++) acc[i][j] = 0.f;

    float4 a4 = *(const float4*)Ap;
    float4 b4 = *(const float4*)Bp;

    for (int kb = 0; kb < K; kb += 8) {
        float4 av = a4, bv = b4;
        if (RELU_A) {
            av.x = fmaxf(av.x, 0.f); av.y = fmaxf(av.y, 0.f);
            av.z = fmaxf(av.z, 0.f); av.w = fmaxf(av.w, 0.f);
        }
        As[acol + 0][arow] = av.x;
        As[acol + 1][arow] = av.y;
        As[acol + 2][arow] = av.z;
        As[acol + 3][arow] = av.w;
        *(float4*)&Bs[brow][bcol] = bv;
        __syncthreads();

        if (kb + 8 < K) {                       // prefetch next k-slice
            a4 = *(const float4*)(Ap + kb + 8);
            b4 = *(const float4*)(Bp + (size_t)(kb + 8) * N);
        }

#pragma unroll
        for (int kk = 0; kk < 8; kk++) {
            float a8[8], b8[8];
            *(float4*)(a8)     = *(const float4*)&As[kk][ty << 3];
            *(float4*)(a8 + 4) = *(const float4*)&As[kk][(ty << 3) + 4];
            *(float4*)(b8)     = *(const float4*)&Bs[kk][tx << 3];
            *(float4*)(b8 + 4) = *(const float4*)&Bs[kk][(tx << 3) + 4];
#pragma unroll
            for (int i = 0; i < 8; i++)
#pragma unroll
                for (int j = 0; j < 8; j++)
                    acc[i][j] = fmaf(a8[i], b8[j], acc[i][j]);
        }
        __syncthreads();
    }

    float bb[8];
    *(float4*)(bb)     = *(const float4*)&bias[bn + (tx << 3)];
    *(float4*)(bb + 4) = *(const float4*)&bias[bn + (tx << 3) + 4];
#pragma unroll
    for (int i = 0; i < 8; i++) {
        float* Cp = C + (size_t)(bm + (ty << 3) + i) * N + bn + (tx << 3);
        *(float4*)(Cp)     = make_float4(acc[i][0] + bb[0], acc[i][1] + bb[1],
                                         acc[i][2] + bb[2], acc[i][3] + bb[3]);
        *(float4*)(Cp + 4) = make_float4(acc[i][4] + bb[4], acc[i][5] + bb[5],
                                         acc[i][6] + bb[6], acc[i][7] + bb[7]);
    }
}

// fused 3-gate pre-GEMM: gridDim.z = 3 selects (B, bias, C)
__global__ void __launch_bounds__(256) gemm_gates_kernel(
    const float* __restrict__ xs,
    const float* __restrict__ Wir, const float* __restrict__ Wiz,
    const float* __restrict__ Win,
    const float* __restrict__ bir, const float* __restrict__ biz,
    const float* __restrict__ bin_,
    float* __restrict__ Gr, float* __restrict__ Gz, float* __restrict__ Gn,
    int M, int N, int K)
{
    const float* B; const float* b; float* C;
    if (blockIdx.z == 0)      { B = Wir; b = bir;  C = Gr; }
    else if (blockIdx.z == 1) { B = Wiz; b = biz;  C = Gz; }
    else                      { B = Win; b = bin_; C = Gn; }
    gemm128_body<false>(xs, B, b, C, M, N, K);
}

// plain GEMM (post dense)
template <bool RELU_A>
__global__ void __launch_bounds__(256) gemm128_kernel(
    const float* __restrict__ A, const float* __restrict__ B,
    const float* __restrict__ bias, float* __restrict__ C,
    int M, int N, int K)
{
    gemm128_body<RELU_A>(A, B, bias, C, M, N, K);
}

// ---------------- persistent GRU recurrence ---------------------------------
// R10 topology (measured best): plain h stores + per-lane0 gpu fence + bar +
// ONE relaxed atomicAdd per CTA on one counter line; tid0 acquire-polls.
// NEW vs R10: 2-deep pipelined counter poll (monotonic counter => safe).
__global__ void __launch_bounds__(256, 1) gru_recurrence_kernel(
    const float* __restrict__ Whr, const float* __restrict__ Whz,
    const float* __restrict__ Whn, const float* __restrict__ bhn,
    const float* __restrict__ init_state)
{
    __shared__ float sh_h[2][D_DIM];       // double buffer: h rows

    const int tid  = threadIdx.x;
    const int warp = tid >> 5, lane = tid & 31;
    const int col  = blockIdx.x * CPC + warp;

    // ---- one-time: weight slice into registers (48 packed f32x2 / gate) ----
    ull wr[16], wz[16], wn[16];
#pragma unroll
    for (int i = 0; i < 16; i++) {
        const int k0 = 2 * (lane + 32 * i);
        const size_t o0 = (size_t)k0 * D_DIM + col;
        const size_t o1 = (size_t)(k0 + 1) * D_DIM + col;
        wr[i] = pack2(Whr[o0], Whr[o1]);
        wz[i] = pack2(Whz[o0], Whz[o1]);
        wn[i] = pack2(Whn[o0], Whn[o1]);
    }
    const float bhn_c = bhn[col];

    float h_prev = init_state[col];
    float gr_c = g_Gr[col], gz_c = g_Gz[col], gn_c = g_Gn[col];

    for (int t = 0; t < T_LEN; t++) {
        float* dst = sh_h[t & 1];

        // ---- wait for step t-1 (tid0: 2-deep pipelined poll of ONE line) ----
        if (t > 0) {
            if (tid == 0) {
                const unsigned* p = &g_cnt[t - 1];
                unsigned c0 = ld_acquire(p);
                unsigned c1 = ld_acquire(p);
                while (c0 < (unsigned)NCTA) {   // counter is monotonic
                    c0 = c1;
                    c1 = ld_acquire(p);
                }
            }
            __syncthreads();               // release CTA to read row t-1
        }

        // ---- prefetch next step's gate pre-activations ----
        float grn = 0.f, gzn = 0.f, gnn = 0.f;
        if (lane == 0 && t + 1 < T_LEN) {
            const size_t o = (size_t)(t + 1) * D_DIM + col;
            grn = __ldg(&g_Gr[o]); gzn = __ldg(&g_Gz[o]); gnn = __ldg(&g_Gn[o]);
        }

        // ---- one-shot coalesced stage of h_{t-1} into smem ----
        if (t == 0) {
            float4 v = ((const float4*)init_state)[tid];
            *(float4*)&dst[tid << 2] = v;
        } else {
            const float4* src = (const float4*)(g_h + (size_t)(t - 1) * D_DIM);
            float4 v = src[tid];           // first touch is post-acquire
            *(float4*)&dst[tid << 2] = v;
        }
        __syncthreads();                   // staging complete

        // ---- packed dot products (3 gates, 2 accumulators each) ----
        const ull* h2 = (const ull*)dst;
        ull ar0 = 0, ar1 = 0, az0 = 0, az1 = 0, an0 = 0, an1 = 0;
#pragma unroll
        for (int i = 0; i < 16; i += 2) {
            ull h0 = h2[lane + 32 * i];
            ull h1 = h2[lane + 32 * (i + 1)];
            fma2(ar0, h0, wr[i]);  fma2(ar1, h1, wr[i + 1]);
            fma2(az0, h0, wz[i]);  fma2(az1, h1, wz[i + 1]);
            fma2(an0, h0, wn[i]);  fma2(an1, h1, wn[i + 1]);
        }
        float lo, hi, ar, az, an;
        unpack2(ar0, lo, hi); ar = lo + hi; unpack2(ar1, lo, hi); ar += lo + hi;
        unpack2(az0, lo, hi); az = lo + hi; unpack2(az1, lo, hi); az += lo + hi;
        unpack2(an0, lo, hi); an = lo + hi; unpack2(an1, lo, hi); an += lo + hi;

#pragma unroll
        for (int o = 16; o > 0; o >>= 1) {
            ar += __shfl_xor_sync(0xFFFFFFFFu, ar, o);
            az += __shfl_xor_sync(0xFFFFFFFFu, az, o);
            an += __shfl_xor_sync(0xFFFFFFFFu, an, o);
        }

        // ---- gate math + publish (lane 0 of each warp) ----
        if (lane == 0) {
            float er = __expf(-(gr_c + ar));
            float r  = __fdividef(1.f, 1.f + er);
            float ez = __expf(-(gz_c + az));
            float z  = __fdividef(1.f, 1.f + ez);
            float nx = gn_c + r * (an + bhn_c);
            float en = __expf(-2.f * nx);
            float n  = __fdividef(1.f - en, 1.f + en);      // tanh(nx)
            float hnew = n + z * (h_prev - n);
            g_h[(size_t)t * D_DIM + col] = hnew;
            __threadfence();               // h store visible before arrive
            h_prev = hnew;
            gr_c = grn; gz_c = gzn; gn_c = gnn;
        }
        __syncthreads();                   // all 8 column stores fenced

        if (tid == 0) atomicAdd(&g_cnt[t], 1u);   // arrive
    }
}

// ---------------- residual + layernorm (in-place on d_out) -----------------
__global__ void __launch_bounds__(256) layernorm_kernel(
    const float* __restrict__ xs, const float* __restrict__ ln_scale,
    const float* __restrict__ ln_bias, float* __restrict__ inout)
{
    __shared__ float red0[8], red1[8];
    const int t = blockIdx.x, tid = threadIdx.x;
    const float* xrow = xs + (size_t)t * D_DIM;
    float* yrow = inout + (size_t)t * D_DIM;

    float v[4];
    float s = 0.f, s2 = 0.f;
#pragma unroll
    for (int i = 0; i < 4; i++) {
        int idx = tid + i * 256;
        float y = xrow[idx] + yrow[idx];
        v[i] = y; s += y; s2 += y * y;
    }
#pragma unroll
    for (int o = 16; o > 0; o >>= 1) {
        s  += __shfl_xor_sync(0xFFFFFFFFu, s,  o);
        s2 += __shfl_xor_sync(0xFFFFFFFFu, s2, o);
    }
    const int warp = tid >> 5, lane = tid & 31;
    if (lane == 0) { red0[warp] = s; red1[warp] = s2; }
    __syncthreads();
    if (warp == 0) {
        float a = (lane < 8) ? red0[lane] : 0.f;
        float b = (lane < 8) ? red1[lane] : 0.f;
#pragma unroll
        for (int o = 4; o > 0; o >>= 1) {
            a += __shfl_xor_sync(0xFFFFFFFFu, a, o);
            b += __shfl_xor_sync(0xFFFFFFFFu, b, o);
        }
        if (lane == 0) { red0[0] = a; red1[0] = b; }
    }
    __syncthreads();

    const float mu   = red0[0] * (1.f / D_DIM);
    const float var  = red1[0] * (1.f / D_DIM) - mu * mu;
    const float rstd = rsqrtf(var + 1e-6f);
#pragma unroll
    for (int i = 0; i < 4; i++) {
        int idx = tid + i * 256;
        yrow[idx] = (v[i] - mu) * rstd * ln_scale[idx] + ln_bias[idx];
    }
}

// ---------------- launcher --------------------------------------------------
extern "C" void kernel_launch(void* const* d_in, const int* in_sizes, int n_in,
                              void* d_out, int out_size)
{
    const float* xs        = (const float*)d_in[0];
    const float* init_st   = (const float*)d_in[1];
    const float* Wir       = (const float*)d_in[2];
    const float* Wiz       = (const float*)d_in[3];
    const float* Win       = (const float*)d_in[4];
    const float* bir       = (const float*)d_in[5];
    const float* biz       = (const float*)d_in[6];
    const float* bin_      = (const float*)d_in[7];
    const float* Whr       = (const float*)d_in[8];
    const float* Whz       = (const float*)d_in[9];
    const float* Whn       = (const float*)d_in[10];
    const float* bhn       = (const float*)d_in[11];
    const float* Wl        = (const float*)d_in[12];
    const float* bl        = (const float*)d_in[13];
    const float* ln_scale  = (const float*)d_in[14];
    const float* ln_bias   = (const float*)d_in[15];
    float* out = (float*)d_out;

    void *pGr, *pGz, *pGn, *pH;
    cudaGetSymbolAddress(&pGr, g_Gr);
    cudaGetSymbolAddress(&pGz, g_Gz);
    cudaGetSymbolAddress(&pGn, g_Gn);
    cudaGetSymbolAddress(&pH,  g_h);

    // 1) clear per-step arrival counters (graph-replay determinism)
    clear_cnt_kernel<<<(T_LEN + 255) / 256, 256>>>();

    // 2) fused input-side gate pre-GEMMs: one launch, 768 CTAs (wave packing)
    dim3 gates_grid(D_DIM / 128, T_LEN / 128, 3);   // (8, 32, 3)
    gemm_gates_kernel<<<gates_grid, 256>>>(xs, Wir, Wiz, Win, bir, biz, bin_,
                                           (float*)pGr, (float*)pGz, (float*)pGn,
                                           T_LEN, D_DIM, D_DIM);

    // 3) sequential recurrence: persistent grid, register-resident weights
    gru_recurrence_kernel<<<NCTA, 256>>>(Whr, Whz, Whn, bhn, init_st);

    // 4) post dense: d_out = relu(h) @ Wl + bl
    dim3 gemm_grid(D_DIM / 128, T_LEN / 128);       // (8, 32)
    gemm128_kernel<true><<<gemm_grid, 256>>>((const float*)pH, Wl, bl, out,
                                             T_LEN, D_DIM, D_DIM);

    // 5) residual + layernorm in-place on d_out
    layernorm_kernel<<<T_LEN, 256>>>(xs, ln_scale, ln_bias, out);
}

// round 14
// speedup vs baseline: 1.3165x; 1.0125x over previous
#include <cuda_runtime.h>

#define T_LEN 4096
#define D_DIM 1024
#define NCTA  128
#define CPC   8      // columns per CTA (= warps per CTA)

typedef unsigned long long ull;

// ---------------- scratch (device globals: no allocation allowed) -----------
__device__ float    g_Gr[T_LEN * D_DIM];
__device__ float    g_Gz[T_LEN * D_DIM];
__device__ float    g_Gn[T_LEN * D_DIM];
__device__ float    g_h [T_LEN * D_DIM];   // plain h history
__device__ unsigned g_cnt[T_LEN];          // per-step arrival counter

// ---------------- PTX helpers ----------------------------------------------
__device__ __forceinline__ ull pack2(float lo, float hi) {
    ull r;
    asm("mov.b64 %0, {%1, %2};" : "=l"(r) : "f"(lo), "f"(hi));
    return r;
}
__device__ __forceinline__ void unpack2(ull v, float& lo, float& hi) {
    asm("mov.b64 {%0, %1}, %2;" : "=f"(lo), "=f"(hi) : "l"(v));
}
__device__ __forceinline__ void fma2(ull& d, ull a, ull b) {
    asm("fma.rn.f32x2 %0, %1, %2, %0;" : "+l"(d) : "l"(a), "l"(b));
}
__device__ __forceinline__ unsigned ld_acquire(const unsigned* p) {
    unsigned v;
    asm volatile("ld.acquire.gpu.u32 %0, [%1];" : "=r"(v) : "l"(p));
    return v;
}

// ---------------- counter clear (fresh each graph replay) -------------------
__global__ void clear_cnt_kernel() {
    int i = blockIdx.x * blockDim.x + threadIdx.x;
    if (i < T_LEN) g_cnt[i] = 0u;
}

// ---------------- fp32 GEMM body: C = (relu?)(A) @ B + bias, 128x128 / 8x8 --
template <bool RELU_A>
__device__ __forceinline__ void gemm128_body(
    const float* __restrict__ A, const float* __restrict__ B,
    const float* __restrict__ bias, float* __restrict__ C,
    int M, int N, int K)
{
    __shared__ float As[8][128];   // As[k][m] (transposed)
    __shared__ float Bs[8][128];   // Bs[k][n]

    const int tid = threadIdx.x;
    const int bm = blockIdx.y << 7, bn = blockIdx.x << 7;

    const int arow = tid >> 1;             // 0..127
    const int acol = (tid & 1) << 2;       // 0 or 4
    const int brow = tid >> 5;             // 0..7
    const int bcol = (tid & 31) << 2;      // 0..124

    const float* Ap = A + (size_t)(bm + arow) * K + acol;
    const float* Bp = B + (size_t)brow * N + bn + bcol;

    const int tx = tid & 15, ty = tid >> 4;

    float acc[8][8];
#pragma unroll
    for (int i = 0; i < 8; i++)
#pragma unroll
        for (int j = 0; j < 8; j++) acc[i][j] = 0.f;

    float4 a4 = *(const float4*)Ap;
    float4 b4 = *(const float4*)Bp;

    for (int kb = 0; kb < K; kb += 8) {
        float4 av = a4, bv = b4;
        if (RELU_A) {
            av.x = fmaxf(av.x, 0.f); av.y = fmaxf(av.y, 0.f);
            av.z = fmaxf(av.z, 0.f); av.w = fmaxf(av.w, 0.f);
        }
        As[acol + 0][arow] = av.x;
        As[acol + 1][arow] = av.y;
        As[acol + 2][arow] = av.z;
        As[acol + 3][arow] = av.w;
        *(float4*)&Bs[brow][bcol] = bv;
        __syncthreads();

        if (kb + 8 < K) {                       // prefetch next k-slice
            a4 = *(const float4*)(Ap + kb + 8);
            b4 = *(const float4*)(Bp + (size_t)(kb + 8) * N);
        }

#pragma unroll
        for (int kk = 0; kk < 8; kk++) {
            float a8[8], b8[8];
            *(float4*)(a8)     = *(const float4*)&As[kk][ty << 3];
            *(float4*)(a8 + 4) = *(const float4*)&As[kk][(ty << 3) + 4];
            *(float4*)(b8)     = *(const float4*)&Bs[kk][tx << 3];
            *(float4*)(b8 + 4) = *(const float4*)&Bs[kk][(tx << 3) + 4];
#pragma unroll
            for (int i = 0; i < 8; i++)
#pragma unroll
                for (int j = 0; j < 8; j++)
                    acc[i][j] = fmaf(a8[i], b8[j], acc[i][j]);
        }
        __syncthreads();
    }

    float bb[8];
    *(float4*)(bb)     = *(const float4*)&bias[bn + (tx << 3)];
    *(float4*)(bb + 4) = *(const float4*)&bias[bn + (tx << 3) + 4];
#pragma unroll
    for (int i = 0; i < 8; i++) {
        float* Cp = C + (size_t)(bm + (ty << 3) + i) * N + bn + (tx << 3);
        *(float4*)(Cp)     = make_float4(acc[i][0] + bb[0], acc[i][1] + bb[1],
                                         acc[i][2] + bb[2], acc[i][3] + bb[3]);
        *(float4*)(Cp + 4) = make_float4(acc[i][4] + bb[4], acc[i][5] + bb[5],
                                         acc[i][6] + bb[6], acc[i][7] + bb[7]);
    }
}

// fused 3-gate pre-GEMM: gridDim.z = 3 selects (B, bias, C)
__global__ void __launch_bounds__(256) gemm_gates_kernel(
    const float* __restrict__ xs,
    const float* __restrict__ Wir, const float* __restrict__ Wiz,
    const float* __restrict__ Win,
    const float* __restrict__ bir, const float* __restrict__ biz,
    const float* __restrict__ bin_,
    float* __restrict__ Gr, float* __restrict__ Gz, float* __restrict__ Gn,
    int M, int N, int K)
{
    const float* B; const float* b; float* C;
    if (blockIdx.z == 0)      { B = Wir; b = bir;  C = Gr; }
    else if (blockIdx.z == 1) { B = Wiz; b = biz;  C = Gz; }
    else                      { B = Win; b = bin_; C = Gn; }
    gemm128_body<false>(xs, B, b, C, M, N, K);
}

// plain GEMM (post dense)
template <bool RELU_A>
__global__ void __launch_bounds__(256) gemm128_kernel(
    const float* __restrict__ A, const float* __restrict__ B,
    const float* __restrict__ bias, float* __restrict__ C,
    int M, int N, int K)
{
    gemm128_body<RELU_A>(A, B, bias, C, M, N, K);
}

// ---------------- persistent GRU recurrence ---------------------------------
// R10 topology (measured best): plain h stores + lane0 gpu fence + bar +
// ONE relaxed atomicAdd per CTA on one counter line; tid0 acquire-polls.
// FIXED vs R13: dual-in-flight poll exits on EITHER value (checks freshest).
__global__ void __launch_bounds__(256, 1) gru_recurrence_kernel(
    const float* __restrict__ Whr, const float* __restrict__ Whz,
    const float* __restrict__ Whn, const float* __restrict__ bhn,
    const float* __restrict__ init_state)
{
    __shared__ float sh_h[2][D_DIM];       // double buffer: h rows

    const int tid  = threadIdx.x;
    const int warp = tid >> 5, lane = tid & 31;
    const int col  = blockIdx.x * CPC + warp;

    // ---- one-time: weight slice into registers (48 packed f32x2 / gate) ----
    ull wr[16], wz[16], wn[16];
#pragma unroll
    for (int i = 0; i < 16; i++) {
        const int k0 = 2 * (lane + 32 * i);
        const size_t o0 = (size_t)k0 * D_DIM + col;
        const size_t o1 = (size_t)(k0 + 1) * D_DIM + col;
        wr[i] = pack2(Whr[o0], Whr[o1]);
        wz[i] = pack2(Whz[o0], Whz[o1]);
        wn[i] = pack2(Whn[o0], Whn[o1]);
    }
    const float bhn_c = bhn[col];

    float h_prev = init_state[col];
    float gr_c = g_Gr[col], gz_c = g_Gz[col], gn_c = g_Gn[col];

    for (int t = 0; t < T_LEN; t++) {
        float* dst = sh_h[t & 1];

        // ---- wait for step t-1 (tid0: two loads in flight, exit on either) --
        if (t > 0) {
            if (tid == 0) {
                const unsigned* p = &g_cnt[t - 1];
                unsigned c0 = ld_acquire(p);
                unsigned c1 = ld_acquire(p);
                while (c0 < (unsigned)NCTA && c1 < (unsigned)NCTA) {
                    c0 = ld_acquire(p);
                    c1 = ld_acquire(p);
                }
            }
            __syncthreads();               // release CTA to read row t-1
        }

        // ---- prefetch next step's gate pre-activations ----
        float grn = 0.f, gzn = 0.f, gnn = 0.f;
        if (lane == 0 && t + 1 < T_LEN) {
            const size_t o = (size_t)(t + 1) * D_DIM + col;
            grn = __ldg(&g_Gr[o]); gzn = __ldg(&g_Gz[o]); gnn = __ldg(&g_Gn[o]);
        }

        // ---- one-shot coalesced stage of h_{t-1} into smem ----
        if (t == 0) {
            float4 v = ((const float4*)init_state)[tid];
            *(float4*)&dst[tid << 2] = v;
        } else {
            const float4* src = (const float4*)(g_h + (size_t)(t - 1) * D_DIM);
            float4 v = src[tid];           // first touch is post-acquire
            *(float4*)&dst[tid << 2] = v;
        }
        __syncthreads();                   // staging complete

        // ---- packed dot products (3 gates, 2 accumulators each) ----
        const ull* h2 = (const ull*)dst;
        ull ar0 = 0, ar1 = 0, az0 = 0, az1 = 0, an0 = 0, an1 = 0;
#pragma unroll
        for (int i = 0; i < 16; i += 2) {
            ull h0 = h2[lane + 32 * i];
            ull h1 = h2[lane + 32 * (i + 1)];
            fma2(ar0, h0, wr[i]);  fma2(ar1, h1, wr[i + 1]);
            fma2(az0, h0, wz[i]);  fma2(az1, h1, wz[i + 1]);
            fma2(an0, h0, wn[i]);  fma2(an1, h1, wn[i + 1]);
        }
        float lo, hi, ar, az, an;
        unpack2(ar0, lo, hi); ar = lo + hi; unpack2(ar1, lo, hi); ar += lo + hi;
        unpack2(az0, lo, hi); az = lo + hi; unpack2(az1, lo, hi); az += lo + hi;
        unpack2(an0, lo, hi); an = lo + hi; unpack2(an1, lo, hi); an += lo + hi;

#pragma unroll
        for (int o = 16; o > 0; o >>= 1) {
            ar += __shfl_xor_sync(0xFFFFFFFFu, ar, o);
            az += __shfl_xor_sync(0xFFFFFFFFu, az, o);
            an += __shfl_xor_sync(0xFFFFFFFFu, an, o);
        }

        // ---- gate math + publish (lane 0 of each warp) ----
        if (lane == 0) {
            float er = __expf(-(gr_c + ar));
            float r  = __fdividef(1.f, 1.f + er);
            float ez = __expf(-(gz_c + az));
            float z  = __fdividef(1.f, 1.f + ez);
            float nx = gn_c + r * (an + bhn_c);
            float en = __expf(-2.f * nx);
            float n  = __fdividef(1.f - en, 1.f + en);      // tanh(nx)
            float hnew = n + z * (h_prev - n);
            g_h[(size_t)t * D_DIM + col] = hnew;
            __threadfence();               // h store visible before arrive
            h_prev = hnew;
            gr_c = grn; gz_c = gzn; gn_c = gnn;
        }
        __syncthreads();                   // all 8 column stores fenced

        if (tid == 0) atomicAdd(&g_cnt[t], 1u);   // arrive
    }
}

// ---------------- residual + layernorm (in-place on d_out) -----------------
__global__ void __launch_bounds__(256) layernorm_kernel(
    const float* __restrict__ xs, const float* __restrict__ ln_scale,
    const float* __restrict__ ln_bias, float* __restrict__ inout)
{
    __shared__ float red0[8], red1[8];
    const int t = blockIdx.x, tid = threadIdx.x;
    const float* xrow = xs + (size_t)t * D_DIM;
    float* yrow = inout + (size_t)t * D_DIM;

    float v[4];
    float s = 0.f, s2 = 0.f;
#pragma unroll
    for (int i = 0; i < 4; i++) {
        int idx = tid + i * 256;
        float y = xrow[idx] + yrow[idx];
        v[i] = y; s += y; s2 += y * y;
    }
#pragma unroll
    for (int o = 16; o > 0; o >>= 1) {
        s  += __shfl_xor_sync(0xFFFFFFFFu, s,  o);
        s2 += __shfl_xor_sync(0xFFFFFFFFu, s2, o);
    }
    const int warp = tid >> 5, lane = tid & 31;
    if (lane == 0) { red0[warp] = s; red1[warp] = s2; }
    __syncthreads();
    if (warp == 0) {
        float a = (lane < 8) ? red0[lane] : 0.f;
        float b = (lane < 8) ? red1[lane] : 0.f;
#pragma unroll
        for (int o = 4; o > 0; o >>= 1) {
            a += __shfl_xor_sync(0xFFFFFFFFu, a, o);
            b += __shfl_xor_sync(0xFFFFFFFFu, b, o);
        }
        if (lane == 0) { red0[0] = a; red1[0] = b; }
    }
    __syncthreads();

    const float mu   = red0[0] * (1.f / D_DIM);
    const float var  = red1[0] * (1.f / D_DIM) - mu * mu;
    const float rstd = rsqrtf(var + 1e-6f);
#pragma unroll
    for (int i = 0; i < 4; i++) {
        int idx = tid + i * 256;
        yrow[idx] = (v[i] - mu) * rstd * ln_scale[idx] + ln_bias[idx];
    }
}

// ---------------- launcher --------------------------------------------------
extern "C" void kernel_launch(void* const* d_in, const int* in_sizes, int n_in,
                              void* d_out, int out_size)
{
    const float* xs        = (const float*)d_in[0];
    const float* init_st   = (const float*)d_in[1];
    const float* Wir       = (const float*)d_in[2];
    const float* Wiz       = (const float*)d_in[3];
    const float* Win       = (const float*)d_in[4];
    const float* bir       = (const float*)d_in[5];
    const float* biz       = (const float*)d_in[6];
    const float* bin_      = (const float*)d_in[7];
    const float* Whr       = (const float*)d_in[8];
    const float* Whz       = (const float*)d_in[9];
    const float* Whn       = (const float*)d_in[10];
    const float* bhn       = (const float*)d_in[11];
    const float* Wl        = (const float*)d_in[12];
    const float* bl        = (const float*)d_in[13];
    const float* ln_scale  = (const float*)d_in[14];
    const float* ln_bias   = (const float*)d_in[15];
    float* out = (float*)d_out;

    void *pGr, *pGz, *pGn, *pH;
    cudaGetSymbolAddress(&pGr, g_Gr);
    cudaGetSymbolAddress(&pGz, g_Gz);
    cudaGetSymbolAddress(&pGn, g_Gn);
    cudaGetSymbolAddress(&pH,  g_h);

    // 1) clear per-step arrival counters (graph-replay determinism)
    clear_cnt_kernel<<<(T_LEN + 255) / 256, 256>>>();

    // 2) fused input-side gate pre-GEMMs: one launch, 768 CTAs (wave packing)
    dim3 gates_grid(D_DIM / 128, T_LEN / 128, 3);   // (8, 32, 3)
    gemm_gates_kernel<<<gates_grid, 256>>>(xs, Wir, Wiz, Win, bir, biz, bin_,
                                           (float*)pGr, (float*)pGz, (float*)pGn,
                                           T_LEN, D_DIM, D_DIM);

    // 3) sequential recurrence: persistent grid, register-resident weights
    gru_recurrence_kernel<<<NCTA, 256>>>(Whr, Whz, Whn, bhn, init_st);

    // 4) post dense: d_out = relu(h) @ Wl + bl
    dim3 gemm_grid(D_DIM / 128, T_LEN / 128);       // (8, 32)
    gemm128_kernel<true><<<gemm_grid, 256>>>((const float*)pH, Wl, bl, out,
                                             T_LEN, D_DIM, D_DIM);

    // 5) residual + layernorm in-place on d_out
    layernorm_kernel<<<T_LEN, 256>>>(xs, ln_scale, ln_bias, out);
}

// round 15
// speedup vs baseline: 1.4638x; 1.1119x over previous
#include <cuda_runtime.h>

#define T_LEN 4096
#define D_DIM 1024
#define NCTA  128
#define CPC   8       // columns per CTA (= warps per CTA)
#define NTILE 32      // time tiles of 128 steps
#define GATE_CTAS 768 // 32 m-tiles x 8 n-tiles x 3 gates

typedef unsigned long long ull;

// ---------------- scratch (device globals: no allocation allowed) -----------
__device__ float    g_Gr[T_LEN * D_DIM];
__device__ float    g_Gz[T_LEN * D_DIM];
__device__ float    g_Gn[T_LEN * D_DIM];
__device__ float    g_h [T_LEN * D_DIM];   // plain h history
__device__ unsigned g_cnt[T_LEN];          // per-step arrival counter
__device__ unsigned g_gcnt[NTILE];         // gates-GEMM tiles done (24 per tile)

// ---------------- PTX helpers ----------------------------------------------
__device__ __forceinline__ ull pack2(float lo, float hi) {
    ull r;
    asm("mov.b64 %0, {%1, %2};" : "=l"(r) : "f"(lo), "f"(hi));
    return r;
}
__device__ __forceinline__ void unpack2(ull v, float& lo, float& hi) {
    asm("mov.b64 {%0, %1}, %2;" : "=f"(lo), "=f"(hi) : "l"(v));
}
__device__ __forceinline__ void fma2(ull& d, ull a, ull b) {
    asm("fma.rn.f32x2 %0, %1, %2, %0;" : "+l"(d) : "l"(a), "l"(b));
}
__device__ __forceinline__ unsigned ld_acquire(const unsigned* p) {
    unsigned v;
    asm volatile("ld.acquire.gpu.u32 %0, [%1];" : "=r"(v) : "l"(p));
    return v;
}

// ---------------- counter clear (fresh each graph replay) -------------------
__global__ void clear_cnt_kernel() {
    int i = blockIdx.x * blockDim.x + threadIdx.x;
    if (i < T_LEN) g_cnt[i] = 0u;
    if (i < NTILE) g_gcnt[i] = 0u;
}

// ---------------- fp32 GEMM body: C = (relu?)(A) @ B + bias, 128x128 / 8x8 --
template <bool RELU_A>
__device__ __forceinline__ void gemm128_body(
    float* smem,
    const float* __restrict__ A, const float* __restrict__ B,
    const float* __restrict__ bias, float* __restrict__ C,
    int bm, int bn, int N, int K)
{
    float (*As)[128] = (float (*)[128])smem;          // As[8][128]
    float (*Bs)[128] = (float (*)[128])(smem + 1024); // Bs[8][128]

    const int tid = threadIdx.x;

    const int arow = tid >> 1;             // 0..127
    const int acol = (tid & 1) << 2;       // 0 or 4
    const int brow = tid >> 5;             // 0..7
    const int bcol = (tid & 31) << 2;      // 0..124

    const float* Ap = A + (size_t)(bm + arow) * K + acol;
    const float* Bp = B + (size_t)brow * N + bn + bcol;

    const int tx = tid & 15, ty = tid >> 4;

    float acc[8][8];
#pragma unroll
    for (int i = 0; i < 8; i++)
#pragma unroll
        for (int j = 0; j < 8; j++) acc[i][j] = 0.f;

    float4 a4 = *(const float4*)Ap;
    float4 b4 = *(const float4*)Bp;

    for (int kb = 0; kb < K; kb += 8) {
        float4 av = a4, bv = b4;
        if (RELU_A) {
            av.x = fmaxf(av.x, 0.f); av.y = fmaxf(av.y, 0.f);
            av.z = fmaxf(av.z, 0.f); av.w = fmaxf(av.w, 0.f);
        }
        As[acol + 0][arow] = av.x;
        As[acol + 1][arow] = av.y;
        As[acol + 2][arow] = av.z;
        As[acol + 3][arow] = av.w;
        *(float4*)&Bs[brow][bcol] = bv;
        __syncthreads();

        if (kb + 8 < K) {                       // prefetch next k-slice
            a4 = *(const float4*)(Ap + kb + 8);
            b4 = *(const float4*)(Bp + (size_t)(kb + 8) * N);
        }

#pragma unroll
        for (int kk = 0; kk < 8; kk++) {
            float a8[8], b8[8];
            *(float4*)(a8)     = *(const float4*)&As[kk][ty << 3];
            *(float4*)(a8 + 4) = *(const float4*)&As[kk][(ty << 3) + 4];
            *(float4*)(b8)     = *(const float4*)&Bs[kk][tx << 3];
            *(float4*)(b8 + 4) = *(const float4*)&Bs[kk][(tx << 3) + 4];
#pragma unroll
            for (int i = 0; i < 8; i++)
#pragma unroll
                for (int j = 0; j < 8; j++)
                    acc[i][j] = fmaf(a8[i], b8[j], acc[i][j]);
        }
        __syncthreads();
    }

    float bb[8];
    *(float4*)(bb)     = *(const float4*)&bias[bn + (tx << 3)];
    *(float4*)(bb + 4) = *(const float4*)&bias[bn + (tx << 3) + 4];
#pragma unroll
    for (int i = 0; i < 8; i++) {
        float* Cp = C + (size_t)(bm + (ty << 3) + i) * N + bn + (tx << 3);
        *(float4*)(Cp)     = make_float4(acc[i][0] + bb[0], acc[i][1] + bb[1],
                                         acc[i][2] + bb[2], acc[i][3] + bb[3]);
        *(float4*)(Cp + 4) = make_float4(acc[i][4] + bb[4], acc[i][5] + bb[5],
                                         acc[i][6] + bb[6], acc[i][7] + bb[7]);
    }
}

// ---------------- fused kernel: recurrence CTAs + gates-GEMM CTAs -----------
// blockIdx 0..127   : R10 recurrence (byte-identical transport), gated on
//                     gates-tile availability via g_gcnt (register-cached).
// blockIdx 128..895 : 3-gate pre-GEMM tiles, m-major; fence+atomic per tile.
__global__ void __launch_bounds__(256, 1) fused_gru_kernel(
    const float* __restrict__ xs,
    const float* __restrict__ Wir, const float* __restrict__ Wiz,
    const float* __restrict__ Win,
    const float* __restrict__ bir, const float* __restrict__ biz,
    const float* __restrict__ bin_,
    const float* __restrict__ Whr, const float* __restrict__ Whz,
    const float* __restrict__ Whn, const float* __restrict__ bhn,
    const float* __restrict__ init_state)
{
    __shared__ float smem[2048];           // union: recurrence 2x1024 | GEMM As+Bs

    if (blockIdx.x >= NCTA) {
        // ================= gates GEMM CTA =================
        const int b    = blockIdx.x - NCTA;      // 0..767
        const int m    = b / 24;                 // time tile (m-major: early first)
        const int rem  = b % 24;
        const int gate = rem >> 3;               // 0..2
        const int n    = rem & 7;                // 0..7
        const float* B; const float* bias; float* C;
        if (gate == 0)      { B = Wir; bias = bir;  C = g_Gr; }
        else if (gate == 1) { B = Wiz; bias = biz;  C = g_Gz; }
        else                { B = Win; bias = bin_; C = g_Gn; }
        gemm128_body<false>(smem, xs, B, bias, C, m << 7, n << 7, D_DIM, D_DIM);
        __threadfence();
        __syncthreads();
        if (threadIdx.x == 0) atomicAdd(&g_gcnt[m], 1u);
        return;
    }

    // ================= recurrence CTA (R10 transport) =================
    float* sh0 = smem;             // buffer 0
    float* sh1 = smem + D_DIM;     // buffer 1

    const int tid  = threadIdx.x;
    const int warp = tid >> 5, lane = tid & 31;
    const int col  = blockIdx.x * CPC + warp;

    // ---- one-time: weight slice into registers (48 packed f32x2 / gate) ----
    ull wr[16], wz[16], wn[16];
#pragma unroll
    for (int i = 0; i < 16; i++) {
        const int k0 = 2 * (lane + 32 * i);
        const size_t o0 = (size_t)k0 * D_DIM + col;
        const size_t o1 = (size_t)(k0 + 1) * D_DIM + col;
        wr[i] = pack2(Whr[o0], Whr[o1]);
        wz[i] = pack2(Whz[o0], Whz[o1]);
        wn[i] = pack2(Whn[o0], Whn[o1]);
    }
    const float bhn_c = bhn[col];

    // ---- wait for gates tile 0 before first G reads ----
    int tile_done = 0;             // tid0's register cache of confirmed tiles
    if (tid == 0) {
        while (ld_acquire(&g_gcnt[0]) < 24u) {}
    }
    __syncthreads();
    tile_done = 1;

    float h_prev = init_state[col];
    float gr_c = g_Gr[col], gz_c = g_Gz[col], gn_c = g_Gn[col];

    for (int t = 0; t < T_LEN; t++) {
        float* dst = (t & 1) ? sh1 : sh0;

        // ---- detect: step t-1 counter + (rarely) next gates tile ----
        if (tid == 0) {
            int need = (t + 1) >> 7;                 // tile of prefetch row t+1
            if (need >= NTILE) need = NTILE - 1;
            while (tile_done <= need) {              // off steady-state path
                if (ld_acquire(&g_gcnt[tile_done]) >= 24u) tile_done++;
            }
            if (t > 0) {
                while (ld_acquire(&g_cnt[t - 1]) < (unsigned)NCTA) {}
            }
        }
        if (t > 0) __syncthreads();                  // release CTA to read row t-1
        else       __syncthreads();                  // tile guard visibility

        // ---- prefetch next step's gate pre-activations ----
        float grn = 0.f, gzn = 0.f, gnn = 0.f;
        if (lane == 0 && t + 1 < T_LEN) {
            const size_t o = (size_t)(t + 1) * D_DIM + col;
            grn = __ldg(&g_Gr[o]); gzn = __ldg(&g_Gz[o]); gnn = __ldg(&g_Gn[o]);
        }

        // ---- one-shot coalesced stage of h_{t-1} into smem ----
        if (t == 0) {
            float4 v = ((const float4*)init_state)[tid];
            *(float4*)&dst[tid << 2] = v;
        } else {
            const float4* src = (const float4*)(g_h + (size_t)(t - 1) * D_DIM);
            float4 v = src[tid];           // first touch is post-acquire
            *(float4*)&dst[tid << 2] = v;
        }
        __syncthreads();                   // staging complete

        // ---- packed dot products (3 gates, 2 accumulators each) ----
        const ull* h2 = (const ull*)dst;
        ull ar0 = 0, ar1 = 0, az0 = 0, az1 = 0, an0 = 0, an1 = 0;
#pragma unroll
        for (int i = 0; i < 16; i += 2) {
            ull h0 = h2[lane + 32 * i];
            ull h1 = h2[lane + 32 * (i + 1)];
            fma2(ar0, h0, wr[i]);  fma2(ar1, h1, wr[i + 1]);
            fma2(az0, h0, wz[i]);  fma2(az1, h1, wz[i + 1]);
            fma2(an0, h0, wn[i]);  fma2(an1, h1, wn[i + 1]);
        }
        float lo, hi, ar, az, an;
        unpack2(ar0, lo, hi); ar = lo + hi; unpack2(ar1, lo, hi); ar += lo + hi;
        unpack2(az0, lo, hi); az = lo + hi; unpack2(az1, lo, hi); az += lo + hi;
        unpack2(an0, lo, hi); an = lo + hi; unpack2(an1, lo, hi); an += lo + hi;

#pragma unroll
        for (int o = 16; o > 0; o >>= 1) {
            ar += __shfl_xor_sync(0xFFFFFFFFu, ar, o);
            az += __shfl_xor_sync(0xFFFFFFFFu, az, o);
            an += __shfl_xor_sync(0xFFFFFFFFu, an, o);
        }

        // ---- gate math + publish (lane 0 of each warp) ----
        if (lane == 0) {
            float er = __expf(-(gr_c + ar));
            float r  = __fdividef(1.f, 1.f + er);
            float ez = __expf(-(gz_c + az));
            float z  = __fdividef(1.f, 1.f + ez);
            float nx = gn_c + r * (an + bhn_c);
            float en = __expf(-2.f * nx);
            float n  = __fdividef(1.f - en, 1.f + en);      // tanh(nx)
            float hnew = n + z * (h_prev - n);
            g_h[(size_t)t * D_DIM + col] = hnew;
            __threadfence();               // h store visible before arrive
            h_prev = hnew;
            gr_c = grn; gz_c = gzn; gn_c = gnn;
        }
        __syncthreads();                   // all 8 column stores fenced

        if (tid == 0) atomicAdd(&g_cnt[t], 1u);   // arrive
    }
}

// ---------------- post dense GEMM (standalone) ------------------------------
template <bool RELU_A>
__global__ void __launch_bounds__(256) gemm128_kernel(
    const float* __restrict__ A, const float* __restrict__ B,
    const float* __restrict__ bias, float* __restrict__ C,
    int M, int N, int K)
{
    __shared__ float smem[2048];
    gemm128_body<RELU_A>(smem, A, B, bias, C,
                         (int)(blockIdx.y << 7), (int)(blockIdx.x << 7), N, K);
}

// ---------------- residual + layernorm (in-place on d_out) -----------------
__global__ void __launch_bounds__(256) layernorm_kernel(
    const float* __restrict__ xs, const float* __restrict__ ln_scale,
    const float* __restrict__ ln_bias, float* __restrict__ inout)
{
    __shared__ float red0[8], red1[8];
    const int t = blockIdx.x, tid = threadIdx.x;
    const float* xrow = xs + (size_t)t * D_DIM;
    float* yrow = inout + (size_t)t * D_DIM;

    float v[4];
    float s = 0.f, s2 = 0.f;
#pragma unroll
    for (int i = 0; i < 4; i++) {
        int idx = tid + i * 256;
        float y = xrow[idx] + yrow[idx];
        v[i] = y; s += y; s2 += y * y;
    }
#pragma unroll
    for (int o = 16; o > 0; o >>= 1) {
        s  += __shfl_xor_sync(0xFFFFFFFFu, s,  o);
        s2 += __shfl_xor_sync(0xFFFFFFFFu, s2, o);
    }
    const int warp = tid >> 5, lane = tid & 31;
    if (lane == 0) { red0[warp] = s; red1[warp] = s2; }
    __syncthreads();
    if (warp == 0) {
        float a = (lane < 8) ? red0[lane] : 0.f;
        float b = (lane < 8) ? red1[lane] : 0.f;
#pragma unroll
        for (int o = 4; o > 0; o >>= 1) {
            a += __shfl_xor_sync(0xFFFFFFFFu, a, o);
            b += __shfl_xor_sync(0xFFFFFFFFu, b, o);
        }
        if (lane == 0) { red0[0] = a; red1[0] = b; }
    }
    __syncthreads();

    const float mu   = red0[0] * (1.f / D_DIM);
    const float var  = red1[0] * (1.f / D_DIM) - mu * mu;
    const float rstd = rsqrtf(var + 1e-6f);
#pragma unroll
    for (int i = 0; i < 4; i++) {
        int idx = tid + i * 256;
        yrow[idx] = (v[i] - mu) * rstd * ln_scale[idx] + ln_bias[idx];
    }
}

// ---------------- launcher --------------------------------------------------
extern "C" void kernel_launch(void* const* d_in, const int* in_sizes, int n_in,
                              void* d_out, int out_size)
{
    const float* xs        = (const float*)d_in[0];
    const float* init_st   = (const float*)d_in[1];
    const float* Wir       = (const float*)d_in[2];
    const float* Wiz       = (const float*)d_in[3];
    const float* Win       = (const float*)d_in[4];
    const float* bir       = (const float*)d_in[5];
    const float* biz       = (const float*)d_in[6];
    const float* bin_      = (const float*)d_in[7];
    const float* Whr       = (const float*)d_in[8];
    const float* Whz       = (const float*)d_in[9];
    const float* Whn       = (const float*)d_in[10];
    const float* bhn       = (const float*)d_in[11];
    const float* Wl        = (const float*)d_in[12];
    const float* bl        = (const float*)d_in[13];
    const float* ln_scale  = (const float*)d_in[14];
    const float* ln_bias   = (const float*)d_in[15];
    float* out = (float*)d_out;

    void* pH;
    cudaGetSymbolAddress(&pH, g_h);

    // 1) clear per-step + per-tile counters (graph-replay determinism)
    clear_cnt_kernel<<<(T_LEN + 255) / 256, 256>>>();

    // 2) fused: recurrence (CTAs 0-127) + gates pre-GEMM (CTAs 128-895),
    //    overlapped; recurrence throttled by g_gcnt tile counters.
    fused_gru_kernel<<<NCTA + GATE_CTAS, 256>>>(
        xs, Wir, Wiz, Win, bir, biz, bin_, Whr, Whz, Whn, bhn, init_st);

    // 3) post dense: d_out = relu(h) @ Wl + bl
    dim3 gemm_grid(D_DIM / 128, T_LEN / 128);       // (8, 32)
    gemm128_kernel<true><<<gemm_grid, 256>>>((const float*)pH, Wl, bl, out,
                                             T_LEN, D_DIM, D_DIM);

    // 4) residual + layernorm in-place on d_out
    layernorm_kernel<<<T_LEN, 256>>>(xs, ln_scale, ln_bias, out);
}

// round 16
// speedup vs baseline: 1.4944x; 1.0210x over previous
#include <cuda_runtime.h>

#define T_LEN 4096
#define D_DIM 1024
#define NCTA  128
#define CPC   8       // columns per CTA (= warps per CTA)
#define NTILE 32      // time tiles of 128 steps
#define GATE_CTAS 768 // 32 m-tiles x 8 n-tiles x 3 gates
#define POST_CTAS 256 // 32 m-tiles x 8 n-tiles

typedef unsigned long long ull;

// ---------------- scratch (device globals: no allocation allowed) -----------
__device__ float    g_Gr[T_LEN * D_DIM];
__device__ float    g_Gz[T_LEN * D_DIM];
__device__ float    g_Gn[T_LEN * D_DIM];
__device__ float    g_h [T_LEN * D_DIM];   // plain h history
__device__ unsigned g_cnt[T_LEN];          // per-step arrival counter
__device__ unsigned g_gcnt[NTILE];         // gates-GEMM tiles done (24 per tile)

// ---------------- PTX helpers ----------------------------------------------
__device__ __forceinline__ ull pack2(float lo, float hi) {
    ull r;
    asm("mov.b64 %0, {%1, %2};" : "=l"(r) : "f"(lo), "f"(hi));
    return r;
}
__device__ __forceinline__ void unpack2(ull v, float& lo, float& hi) {
    asm("mov.b64 {%0, %1}, %2;" : "=f"(lo), "=f"(hi) : "l"(v));
}
__device__ __forceinline__ void fma2(ull& d, ull a, ull b) {
    asm("fma.rn.f32x2 %0, %1, %2, %0;" : "+l"(d) : "l"(a), "l"(b));
}
__device__ __forceinline__ unsigned ld_acquire(const unsigned* p) {
    unsigned v;
    asm volatile("ld.acquire.gpu.u32 %0, [%1];" : "=r"(v) : "l"(p));
    return v;
}

// ---------------- counter clear (fresh each graph replay) -------------------
__global__ void clear_cnt_kernel() {
    int i = blockIdx.x * blockDim.x + threadIdx.x;
    if (i < T_LEN) g_cnt[i] = 0u;
    if (i < NTILE) g_gcnt[i] = 0u;
}

// ---------------- fp32 GEMM body: C = (relu?)(A) @ B + bias, 128x128 / 8x8 --
template <bool RELU_A>
__device__ __forceinline__ void gemm128_body(
    float* smem,
    const float* __restrict__ A, const float* __restrict__ B,
    const float* __restrict__ bias, float* __restrict__ C,
    int bm, int bn, int N, int K)
{
    float (*As)[128] = (float (*)[128])smem;          // As[8][128]
    float (*Bs)[128] = (float (*)[128])(smem + 1024); // Bs[8][128]

    const int tid = threadIdx.x;

    const int arow = tid >> 1;             // 0..127
    const int acol = (tid & 1) << 2;       // 0 or 4
    const int brow = tid >> 5;             // 0..7
    const int bcol = (tid & 31) << 2;      // 0..124

    const float* Ap = A + (size_t)(bm + arow) * K + acol;
    const float* Bp = B + (size_t)brow * N + bn + bcol;

    const int tx = tid & 15, ty = tid >> 4;

    float acc[8][8];
#pragma unroll
    for (int i = 0; i < 8; i++)
#pragma unroll
        for (int j = 0; j < 8; j++) acc[i][j] = 0.f;

    float4 a4 = *(const float4*)Ap;
    float4 b4 = *(const float4*)Bp;

    for (int kb = 0; kb < K; kb += 8) {
        float4 av = a4, bv = b4;
        if (RELU_A) {
            av.x = fmaxf(av.x, 0.f); av.y = fmaxf(av.y, 0.f);
            av.z = fmaxf(av.z, 0.f); av.w = fmaxf(av.w, 0.f);
        }
        As[acol + 0][arow] = av.x;
        As[acol + 1][arow] = av.y;
        As[acol + 2][arow] = av.z;
        As[acol + 3][arow] = av.w;
        *(float4*)&Bs[brow][bcol] = bv;
        __syncthreads();

        if (kb + 8 < K) {                       // prefetch next k-slice
            a4 = *(const float4*)(Ap + kb + 8);
            b4 = *(const float4*)(Bp + (size_t)(kb + 8) * N);
        }

#pragma unroll
        for (int kk = 0; kk < 8; kk++) {
            float a8[8], b8[8];
            *(float4*)(a8)     = *(const float4*)&As[kk][ty << 3];
            *(float4*)(a8 + 4) = *(const float4*)&As[kk][(ty << 3) + 4];
            *(float4*)(b8)     = *(const float4*)&Bs[kk][tx << 3];
            *(float4*)(b8 + 4) = *(const float4*)&Bs[kk][(tx << 3) + 4];
#pragma unroll
            for (int i = 0; i < 8; i++)
#pragma unroll
                for (int j = 0; j < 8; j++)
                    acc[i][j] = fmaf(a8[i], b8[j], acc[i][j]);
        }
        __syncthreads();
    }

    float bb[8];
    *(float4*)(bb)     = *(const float4*)&bias[bn + (tx << 3)];
    *(float4*)(bb + 4) = *(const float4*)&bias[bn + (tx << 3) + 4];
#pragma unroll
    for (int i = 0; i < 8; i++) {
        float* Cp = C + (size_t)(bm + (ty << 3) + i) * N + bn + (tx << 3);
        *(float4*)(Cp)     = make_float4(acc[i][0] + bb[0], acc[i][1] + bb[1],
                                         acc[i][2] + bb[2], acc[i][3] + bb[3]);
        *(float4*)(Cp + 4) = make_float4(acc[i][4] + bb[4], acc[i][5] + bb[5],
                                         acc[i][6] + bb[6], acc[i][7] + bb[7]);
    }
}

// ---------------- fused kernel: recurrence + gates GEMM + post GEMM ---------
// blockIdx 0..127    : R10 recurrence (byte-identical transport)
// blockIdx 128..895  : 3-gate pre-GEMM tiles (m-major), fence+atomic per tile
// blockIdx 896..1151 : post dense relu(h)@Wl tiles; each waits on the step
//                      counter of its m-tile's last row, then runs.
__global__ void __launch_bounds__(256, 1) fused_gru_kernel(
    const float* __restrict__ xs,
    const float* __restrict__ Wir, const float* __restrict__ Wiz,
    const float* __restrict__ Win,
    const float* __restrict__ bir, const float* __restrict__ biz,
    const float* __restrict__ bin_,
    const float* __restrict__ Whr, const float* __restrict__ Whz,
    const float* __restrict__ Whn, const float* __restrict__ bhn,
    const float* __restrict__ init_state,
    const float* __restrict__ Wl, const float* __restrict__ bl,
    float* __restrict__ out)
{
    __shared__ float smem[2048];           // union: recurrence 2x1024 | GEMM As+Bs

    if (blockIdx.x >= NCTA + GATE_CTAS) {
        // ================= post-GEMM CTA =================
        const int b = blockIdx.x - (NCTA + GATE_CTAS);   // 0..255
        const int m = b >> 3;                            // m-tile (m-major)
        const int n = b & 7;
        if (threadIdx.x == 0) {
            const unsigned* p = &g_cnt[(m << 7) + 127];  // last step of tile
            while (ld_acquire(p) < (unsigned)NCTA) {}
        }
        __syncthreads();
        gemm128_body<true>(smem, g_h, Wl, bl, out, m << 7, n << 7, D_DIM, D_DIM);
        return;
    }

    if (blockIdx.x >= NCTA) {
        // ================= gates GEMM CTA =================
        const int b    = blockIdx.x - NCTA;      // 0..767
        const int m    = b / 24;                 // time tile (m-major: early first)
        const int rem  = b % 24;
        const int gate = rem >> 3;               // 0..2
        const int n    = rem & 7;                // 0..7
        const float* B; const float* bias; float* C;
        if (gate == 0)      { B = Wir; bias = bir;  C = g_Gr; }
        else if (gate == 1) { B = Wiz; bias = biz;  C = g_Gz; }
        else                { B = Win; bias = bin_; C = g_Gn; }
        gemm128_body<false>(smem, xs, B, bias, C, m << 7, n << 7, D_DIM, D_DIM);
        __threadfence();
        __syncthreads();
        if (threadIdx.x == 0) atomicAdd(&g_gcnt[m], 1u);
        return;
    }

    // ================= recurrence CTA (R10 transport) =================
    float* sh0 = smem;             // buffer 0
    float* sh1 = smem + D_DIM;     // buffer 1

    const int tid  = threadIdx.x;
    const int warp = tid >> 5, lane = tid & 31;
    const int col  = blockIdx.x * CPC + warp;

    // ---- one-time: weight slice into registers (48 packed f32x2 / gate) ----
    ull wr[16], wz[16], wn[16];
#pragma unroll
    for (int i = 0; i < 16; i++) {
        const int k0 = 2 * (lane + 32 * i);
        const size_t o0 = (size_t)k0 * D_DIM + col;
        const size_t o1 = (size_t)(k0 + 1) * D_DIM + col;
        wr[i] = pack2(Whr[o0], Whr[o1]);
        wz[i] = pack2(Whz[o0], Whz[o1]);
        wn[i] = pack2(Whn[o0], Whn[o1]);
    }
    const float bhn_c = bhn[col];

    // ---- wait for gates tile 0 before first G reads ----
    int tile_done = 0;             // tid0's register cache of confirmed tiles
    if (tid == 0) {
        while (ld_acquire(&g_gcnt[0]) < 24u) {}
    }
    __syncthreads();
    tile_done = 1;

    float h_prev = init_state[col];
    float gr_c = g_Gr[col], gz_c = g_Gz[col], gn_c = g_Gn[col];

    for (int t = 0; t < T_LEN; t++) {
        float* dst = (t & 1) ? sh1 : sh0;

        // ---- detect: step t-1 counter + (rarely) next gates tile ----
        if (tid == 0) {
            int need = (t + 1) >> 7;                 // tile of prefetch row t+1
            if (need >= NTILE) need = NTILE - 1;
            while (tile_done <= need) {              // off steady-state path
                if (ld_acquire(&g_gcnt[tile_done]) >= 24u) tile_done++;
            }
            if (t > 0) {
                while (ld_acquire(&g_cnt[t - 1]) < (unsigned)NCTA) {}
            }
        }
        __syncthreads();                             // release CTA

        // ---- prefetch next step's gate pre-activations ----
        float grn = 0.f, gzn = 0.f, gnn = 0.f;
        if (lane == 0 && t + 1 < T_LEN) {
            const size_t o = (size_t)(t + 1) * D_DIM + col;
            grn = __ldg(&g_Gr[o]); gzn = __ldg(&g_Gz[o]); gnn = __ldg(&g_Gn[o]);
        }

        // ---- one-shot coalesced stage of h_{t-1} into smem ----
        if (t == 0) {
            float4 v = ((const float4*)init_state)[tid];
            *(float4*)&dst[tid << 2] = v;
        } else {
            const float4* src = (const float4*)(g_h + (size_t)(t - 1) * D_DIM);
            float4 v = src[tid];           // first touch is post-acquire
            *(float4*)&dst[tid << 2] = v;
        }
        __syncthreads();                   // staging complete

        // ---- packed dot products (3 gates, 2 accumulators each) ----
        const ull* h2 = (const ull*)dst;
        ull ar0 = 0, ar1 = 0, az0 = 0, az1 = 0, an0 = 0, an1 = 0;
#pragma unroll
        for (int i = 0; i < 16; i += 2) {
            ull h0 = h2[lane + 32 * i];
            ull h1 = h2[lane + 32 * (i + 1)];
            fma2(ar0, h0, wr[i]);  fma2(ar1, h1, wr[i + 1]);
            fma2(az0, h0, wz[i]);  fma2(az1, h1, wz[i + 1]);
            fma2(an0, h0, wn[i]);  fma2(an1, h1, wn[i + 1]);
        }
        float lo, hi, ar, az, an;
        unpack2(ar0, lo, hi); ar = lo + hi; unpack2(ar1, lo, hi); ar += lo + hi;
        unpack2(az0, lo, hi); az = lo + hi; unpack2(az1, lo, hi); az += lo + hi;
        unpack2(an0, lo, hi); an = lo + hi; unpack2(an1, lo, hi); an += lo + hi;

#pragma unroll
        for (int o = 16; o > 0; o >>= 1) {
            ar += __shfl_xor_sync(0xFFFFFFFFu, ar, o);
            az += __shfl_xor_sync(0xFFFFFFFFu, az, o);
            an += __shfl_xor_sync(0xFFFFFFFFu, an, o);
        }

        // ---- gate math + publish (lane 0 of each warp) ----
        if (lane == 0) {
            float er = __expf(-(gr_c + ar));
            float r  = __fdividef(1.f, 1.f + er);
            float ez = __expf(-(gz_c + az));
            float z  = __fdividef(1.f, 1.f + ez);
            float nx = gn_c + r * (an + bhn_c);
            float en = __expf(-2.f * nx);
            float n  = __fdividef(1.f - en, 1.f + en);      // tanh(nx)
            float hnew = n + z * (h_prev - n);
            g_h[(size_t)t * D_DIM + col] = hnew;
            __threadfence();               // h store visible before arrive
            h_prev = hnew;
            gr_c = grn; gz_c = gzn; gn_c = gnn;
        }
        __syncthreads();                   // all 8 column stores fenced

        if (tid == 0) atomicAdd(&g_cnt[t], 1u);   // arrive
    }
}

// ---------------- residual + layernorm (in-place on d_out) -----------------
__global__ void __launch_bounds__(256) layernorm_kernel(
    const float* __restrict__ xs, const float* __restrict__ ln_scale,
    const float* __restrict__ ln_bias, float* __restrict__ inout)
{
    __shared__ float red0[8], red1[8];
    const int t = blockIdx.x, tid = threadIdx.x;
    const float* xrow = xs + (size_t)t * D_DIM;
    float* yrow = inout + (size_t)t * D_DIM;

    float v[4];
    float s = 0.f, s2 = 0.f;
#pragma unroll
    for (int i = 0; i < 4; i++) {
        int idx = tid + i * 256;
        float y = xrow[idx] + yrow[idx];
        v[i] = y; s += y; s2 += y * y;
    }
#pragma unroll
    for (int o = 16; o > 0; o >>= 1) {
        s  += __shfl_xor_sync(0xFFFFFFFFu, s,  o);
        s2 += __shfl_xor_sync(0xFFFFFFFFu, s2, o);
    }
    const int warp = tid >> 5, lane = tid & 31;
    if (lane == 0) { red0[warp] = s; red1[warp] = s2; }
    __syncthreads();
    if (warp == 0) {
        float a = (lane < 8) ? red0[lane] : 0.f;
        float b = (lane < 8) ? red1[lane] : 0.f;
#pragma unroll
        for (int o = 4; o > 0; o >>= 1) {
            a += __shfl_xor_sync(0xFFFFFFFFu, a, o);
            b += __shfl_xor_sync(0xFFFFFFFFu, b, o);
        }
        if (lane == 0) { red0[0] = a; red1[0] = b; }
    }
    __syncthreads();

    const float mu   = red0[0] * (1.f / D_DIM);
    const float var  = red1[0] * (1.f / D_DIM) - mu * mu;
    const float rstd = rsqrtf(var + 1e-6f);
#pragma unroll
    for (int i = 0; i < 4; i++) {
        int idx = tid + i * 256;
        yrow[idx] = (v[i] - mu) * rstd * ln_scale[idx] + ln_bias[idx];
    }
}

// ---------------- launcher --------------------------------------------------
extern "C" void kernel_launch(void* const* d_in, const int* in_sizes, int n_in,
                              void* d_out, int out_size)
{
    const float* xs        = (const float*)d_in[0];
    const float* init_st   = (const float*)d_in[1];
    const float* Wir       = (const float*)d_in[2];
    const float* Wiz       = (const float*)d_in[3];
    const float* Win       = (const float*)d_in[4];
    const float* bir       = (const float*)d_in[5];
    const float* biz       = (const float*)d_in[6];
    const float* bin_      = (const float*)d_in[7];
    const float* Whr       = (const float*)d_in[8];
    const float* Whz       = (const float*)d_in[9];
    const float* Whn       = (const float*)d_in[10];
    const float* bhn       = (const float*)d_in[11];
    const float* Wl        = (const float*)d_in[12];
    const float* bl        = (const float*)d_in[13];
    const float* ln_scale  = (const float*)d_in[14];
    const float* ln_bias   = (const float*)d_in[15];
    float* out = (float*)d_out;

    // 1) clear per-step + per-tile counters (graph-replay determinism)
    clear_cnt_kernel<<<(T_LEN + 255) / 256, 256>>>();

    // 2) fused: recurrence + gates pre-GEMM + post dense GEMM, all overlapped
    fused_gru_kernel<<<NCTA + GATE_CTAS + POST_CTAS, 256>>>(
        xs, Wir, Wiz, Win, bir, biz, bin_, Whr, Whz, Whn, bhn, init_st,
        Wl, bl, out);

    // 3) residual + layernorm in-place on d_out
    layernorm_kernel<<<T_LEN, 256>>>(xs, ln_scale, ln_bias, out);
}

// round 17
// speedup vs baseline: 1.6065x; 1.0750x over previous
#include <cuda_runtime.h>

#define T_LEN 4096
#define D_DIM 1024
#define NCTA  128
#define CPC   8       // columns per CTA (= warps per CTA)
#define NTILE 32      // time tiles of 128 steps
#define GATE_CTAS 768 // 32 m-tiles x 8 n-tiles x 3 gates
#define POST_CTAS 256 // 32 m-tiles x 8 n-tiles
#define LN_CTAS   (T_LEN / 8)   // 512 CTAs x 8 rows each
#define CSTRIDE 32    // pad counters: one 128B line per step

typedef unsigned long long ull;

// ---------------- scratch (device globals: no allocation allowed) -----------
__device__ float    g_Gr[T_LEN * D_DIM];
__device__ float    g_Gz[T_LEN * D_DIM];
__device__ float    g_Gn[T_LEN * D_DIM];
__device__ float    g_h [T_LEN * D_DIM];       // plain h history
__device__ unsigned g_cnt[T_LEN * CSTRIDE];    // per-step counter, line-padded
__device__ unsigned g_gcnt[NTILE * CSTRIDE];   // gates tiles done (24 per tile)
__device__ unsigned g_pcnt[NTILE * CSTRIDE];   // post tiles done (8 per tile)

// ---------------- PTX helpers ----------------------------------------------
__device__ __forceinline__ ull pack2(float lo, float hi) {
    ull r;
    asm("mov.b64 %0, {%1, %2};" : "=l"(r) : "f"(lo), "f"(hi));
    return r;
}
__device__ __forceinline__ void unpack2(ull v, float& lo, float& hi) {
    asm("mov.b64 {%0, %1}, %2;" : "=f"(lo), "=f"(hi) : "l"(v));
}
__device__ __forceinline__ void fma2(ull& d, ull a, ull b) {
    asm("fma.rn.f32x2 %0, %1, %2, %0;" : "+l"(d) : "l"(a), "l"(b));
}
__device__ __forceinline__ unsigned ld_acquire(const unsigned* p) {
    unsigned v;
    asm volatile("ld.acquire.gpu.u32 %0, [%1];" : "=r"(v) : "l"(p));
    return v;
}
__device__ __forceinline__ void atom_add_release(unsigned* p, unsigned v) {
    unsigned old;
    asm volatile("atom.release.gpu.global.add.u32 %0, [%1], %2;"
                 : "=r"(old) : "l"(p), "r"(v) : "memory");
}

// ---------------- counter clear (fresh each graph replay) -------------------
__global__ void clear_cnt_kernel() {
    int i = blockIdx.x * blockDim.x + threadIdx.x;
    if (i < T_LEN) g_cnt[i * CSTRIDE] = 0u;
    if (i < NTILE) { g_gcnt[i * CSTRIDE] = 0u; g_pcnt[i * CSTRIDE] = 0u; }
}

// ---------------- fp32 GEMM body: C = (relu?)(A) @ B + bias, 128x128 / 8x8 --
template <bool RELU_A>
__device__ __forceinline__ void gemm128_body(
    float* smem,
    const float* __restrict__ A, const float* __restrict__ B,
    const float* __restrict__ bias, float* __restrict__ C,
    int bm, int bn, int N, int K)
{
    float (*As)[128] = (float (*)[128])smem;          // As[8][128]
    float (*Bs)[128] = (float (*)[128])(smem + 1024); // Bs[8][128]

    const int tid = threadIdx.x;

    const int arow = tid >> 1;             // 0..127
    const int acol = (tid & 1) << 2;       // 0 or 4
    const int brow = tid >> 5;             // 0..7
    const int bcol = (tid & 31) << 2;      // 0..124

    const float* Ap = A + (size_t)(bm + arow) * K + acol;
    const float* Bp = B + (size_t)brow * N + bn + bcol;

    const int tx = tid & 15, ty = tid >> 4;

    float acc[8][8];
#pragma unroll
    for (int i = 0; i < 8; i++)
#pragma unroll
        for (int j = 0; j < 8; j++) acc[i][j] = 0.f;

    float4 a4 = *(const float4*)Ap;
    float4 b4 = *(const float4*)Bp;

    for (int kb = 0; kb < K; kb += 8) {
        float4 av = a4, bv = b4;
        if (RELU_A) {
            av.x = fmaxf(av.x, 0.f); av.y = fmaxf(av.y, 0.f);
            av.z = fmaxf(av.z, 0.f); av.w = fmaxf(av.w, 0.f);
        }
        As[acol + 0][arow] = av.x;
        As[acol + 1][arow] = av.y;
        As[acol + 2][arow] = av.z;
        As[acol + 3][arow] = av.w;
        *(float4*)&Bs[brow][bcol] = bv;
        __syncthreads();

        if (kb + 8 < K) {                       // prefetch next k-slice
            a4 = *(const float4*)(Ap + kb + 8);
            b4 = *(const float4*)(Bp + (size_t)(kb + 8) * N);
        }

#pragma unroll
        for (int kk = 0; kk < 8; kk++) {
            float a8[8], b8[8];
            *(float4*)(a8)     = *(const float4*)&As[kk][ty << 3];
            *(float4*)(a8 + 4) = *(const float4*)&As[kk][(ty << 3) + 4];
            *(float4*)(b8)     = *(const float4*)&Bs[kk][tx << 3];
            *(float4*)(b8 + 4) = *(const float4*)&Bs[kk][(tx << 3) + 4];
#pragma unroll
            for (int i = 0; i < 8; i++)
#pragma unroll
                for (int j = 0; j < 8; j++)
                    acc[i][j] = fmaf(a8[i], b8[j], acc[i][j]);
        }
        __syncthreads();
    }

    float bb[8];
    *(float4*)(bb)     = *(const float4*)&bias[bn + (tx << 3)];
    *(float4*)(bb + 4) = *(const float4*)&bias[bn + (tx << 3) + 4];
#pragma unroll
    for (int i = 0; i < 8; i++) {
        float* Cp = C + (size_t)(bm + (ty << 3) + i) * N + bn + (tx << 3);
        *(float4*)(Cp)     = make_float4(acc[i][0] + bb[0], acc[i][1] + bb[1],
                                         acc[i][2] + bb[2], acc[i][3] + bb[3]);
        *(float4*)(Cp + 4) = make_float4(acc[i][4] + bb[4], acc[i][5] + bb[5],
                                         acc[i][6] + bb[6], acc[i][7] + bb[7]);
    }
}

// ---------------- layernorm row body ----------------------------------------
__device__ __forceinline__ void ln_row(
    const float* __restrict__ xs, const float* __restrict__ ln_scale,
    const float* __restrict__ ln_bias, float* __restrict__ inout,
    int t, int tid)
{
    const float* xrow = xs + (size_t)t * D_DIM;
    float* yrow = inout + (size_t)t * D_DIM;
    const int lane = tid & 31;

    float v[4];
    float s = 0.f, s2 = 0.f;
#pragma unroll
    for (int i = 0; i < 4; i++) {
        int idx = (tid & 255) + i * 256;
        float y = xrow[idx] + yrow[idx];
        v[i] = y; s += y; s2 += y * y;
    }
#pragma unroll
    for (int o = 16; o > 0; o >>= 1) {
        s  += __shfl_xor_sync(0xFFFFFFFFu, s,  o);
        s2 += __shfl_xor_sync(0xFFFFFFFFu, s2, o);
    }
    __shared__ float red0[8], red1[8];
    const int warp = (tid & 255) >> 5;
    if (lane == 0) { red0[warp] = s; red1[warp] = s2; }
    __syncthreads();
    float a = red0[lane & 7], b = red1[lane & 7];
#pragma unroll
    for (int o = 4; o > 0; o >>= 1) {
        a += __shfl_xor_sync(0xFFFFFFFFu, a, o);
        b += __shfl_xor_sync(0xFFFFFFFFu, b, o);
    }
    a = __shfl_sync(0xFFFFFFFFu, a, 0);
    b = __shfl_sync(0xFFFFFFFFu, b, 0);

    const float mu   = a * (1.f / D_DIM);
    const float var  = b * (1.f / D_DIM) - mu * mu;
    const float rstd = rsqrtf(var + 1e-6f);
#pragma unroll
    for (int i = 0; i < 4; i++) {
        int idx = (tid & 255) + i * 256;
        yrow[idx] = (v[i] - mu) * rstd * ln_scale[idx] + ln_bias[idx];
    }
    __syncthreads();   // red0/red1 reuse
}

// ---------------- fused kernel: recurrence + gates + post + layernorm -------
// blockIdx 0..127     : R10 recurrence (proven transport)
// blockIdx 128..895   : 3-gate pre-GEMM tiles (m-major)
// blockIdx 896..1151  : post dense relu(h)@Wl tiles, gated on step counters
// blockIdx 1152..1663 : layernorm, 8 rows each, gated on post tile counters
__global__ void __launch_bounds__(256, 1) fused_gru_kernel(
    const float* __restrict__ xs,
    const float* __restrict__ Wir, const float* __restrict__ Wiz,
    const float* __restrict__ Win,
    const float* __restrict__ bir, const float* __restrict__ biz,
    const float* __restrict__ bin_,
    const float* __restrict__ Whr, const float* __restrict__ Whz,
    const float* __restrict__ Whn, const float* __restrict__ bhn,
    const float* __restrict__ init_state,
    const float* __restrict__ Wl, const float* __restrict__ bl,
    const float* __restrict__ ln_scale, const float* __restrict__ ln_bias,
    float* __restrict__ out)
{
    __shared__ float smem[2048];           // union across roles

    if (blockIdx.x >= NCTA + GATE_CTAS + POST_CTAS) {
        // ================= layernorm CTA (8 rows) =================
        const int b  = blockIdx.x - (NCTA + GATE_CTAS + POST_CTAS); // 0..511
        const int t0 = b * 8;                                        // first row
        const int m  = t0 >> 7;                                      // m-tile
        if (threadIdx.x == 0) {
            const unsigned* p = &g_pcnt[m * CSTRIDE];
            while (ld_acquire(p) < 8u) {}
        }
        __syncthreads();
        for (int i = 0; i < 8; i++)
            ln_row(xs, ln_scale, ln_bias, out, t0 + i, threadIdx.x);
        return;
    }

    if (blockIdx.x >= NCTA + GATE_CTAS) {
        // ================= post-GEMM CTA =================
        const int b = blockIdx.x - (NCTA + GATE_CTAS);   // 0..255
        const int m = b >> 3;                            // m-tile (m-major)
        const int n = b & 7;
        if (threadIdx.x == 0) {
            const unsigned* p = &g_cnt[((m << 7) + 127) * CSTRIDE];
            while (ld_acquire(p) < (unsigned)NCTA) {}
        }
        __syncthreads();
        gemm128_body<true>(smem, g_h, Wl, bl, out, m << 7, n << 7, D_DIM, D_DIM);
        __syncthreads();
        if (threadIdx.x == 0) atom_add_release(&g_pcnt[m * CSTRIDE], 1u);
        return;
    }

    if (blockIdx.x >= NCTA) {
        // ================= gates GEMM CTA =================
        const int b    = blockIdx.x - NCTA;      // 0..767
        const int m    = b / 24;                 // time tile (m-major: early first)
        const int rem  = b % 24;
        const int gate = rem >> 3;               // 0..2
        const int n    = rem & 7;                // 0..7
        const float* B; const float* bias; float* C;
        if (gate == 0)      { B = Wir; bias = bir;  C = g_Gr; }
        else if (gate == 1) { B = Wiz; bias = biz;  C = g_Gz; }
        else                { B = Win; bias = bin_; C = g_Gn; }
        gemm128_body<false>(smem, xs, B, bias, C, m << 7, n << 7, D_DIM, D_DIM);
        __syncthreads();
        if (threadIdx.x == 0) atom_add_release(&g_gcnt[m * CSTRIDE], 1u);
        return;
    }

    // ================= recurrence CTA (R10 transport) =================
    float* sh0 = smem;             // buffer 0
    float* sh1 = smem + D_DIM;     // buffer 1

    const int tid  = threadIdx.x;
    const int warp = tid >> 5, lane = tid & 31;
    const int col  = blockIdx.x * CPC + warp;

    // ---- one-time: weight slice into registers (48 packed f32x2 / gate) ----
    ull wr[16], wz[16], wn[16];
#pragma unroll
    for (int i = 0; i < 16; i++) {
        const int k0 = 2 * (lane + 32 * i);
        const size_t o0 = (size_t)k0 * D_DIM + col;
        const size_t o1 = (size_t)(k0 + 1) * D_DIM + col;
        wr[i] = pack2(Whr[o0], Whr[o1]);
        wz[i] = pack2(Whz[o0], Whz[o1]);
        wn[i] = pack2(Whn[o0], Whn[o1]);
    }
    const float bhn_c = bhn[col];

    // ---- wait for gates tile 0 before first G reads ----
    int tile_done = 0;             // tid0's register cache of confirmed tiles
    if (tid == 0) {
        while (ld_acquire(&g_gcnt[0]) < 24u) {}
    }
    __syncthreads();
    tile_done = 1;

    float h_prev = init_state[col];
    float gr_c = g_Gr[col], gz_c = g_Gz[col], gn_c = g_Gn[col];

    for (int t = 0; t < T_LEN; t++) {
        float* dst = (t & 1) ? sh1 : sh0;

        // ---- detect: step t-1 counter + (rarely) next gates tile ----
        if (tid == 0) {
            int need = (t + 1) >> 7;                 // tile of prefetch row t+1
            if (need >= NTILE) need = NTILE - 1;
            while (tile_done <= need) {              // off steady-state path
                if (ld_acquire(&g_gcnt[tile_done * CSTRIDE]) >= 24u) tile_done++;
            }
            if (t > 0) {
                while (ld_acquire(&g_cnt[(t - 1) * CSTRIDE]) < (unsigned)NCTA) {}
            }
        }
        __syncthreads();                             // release CTA

        // ---- prefetch next step's gate pre-activations ----
        float grn = 0.f, gzn = 0.f, gnn = 0.f;
        if (lane == 0 && t + 1 < T_LEN) {
            const size_t o = (size_t)(t + 1) * D_DIM + col;
            grn = __ldg(&g_Gr[o]); gzn = __ldg(&g_Gz[o]); gnn = __ldg(&g_Gn[o]);
        }

        // ---- one-shot coalesced stage of h_{t-1} into smem ----
        if (t == 0) {
            float4 v = ((const float4*)init_state)[tid];
            *(float4*)&dst[tid << 2] = v;
        } else {
            const float4* src = (const float4*)(g_h + (size_t)(t - 1) * D_DIM);
            float4 v = src[tid];           // first touch is post-acquire
            *(float4*)&dst[tid << 2] = v;
        }
        __syncthreads();                   // staging complete

        // ---- packed dot products (3 gates, 2 accumulators each) ----
        const ull* h2 = (const ull*)dst;
        ull ar0 = 0, ar1 = 0, az0 = 0, az1 = 0, an0 = 0, an1 = 0;
#pragma unroll
        for (int i = 0; i < 16; i += 2) {
            ull h0 = h2[lane + 32 * i];
            ull h1 = h2[lane + 32 * (i + 1)];
            fma2(ar0, h0, wr[i]);  fma2(ar1, h1, wr[i + 1]);
            fma2(az0, h0, wz[i]);  fma2(az1, h1, wz[i + 1]);
            fma2(an0, h0, wn[i]);  fma2(an1, h1, wn[i + 1]);
        }
        float lo, hi, ar, az, an;
        unpack2(ar0, lo, hi); ar = lo + hi; unpack2(ar1, lo, hi); ar += lo + hi;
        unpack2(az0, lo, hi); az = lo + hi; unpack2(az1, lo, hi); az += lo + hi;
        unpack2(an0, lo, hi); an = lo + hi; unpack2(an1, lo, hi); an += lo + hi;

#pragma unroll
        for (int o = 16; o > 0; o >>= 1) {
            ar += __shfl_xor_sync(0xFFFFFFFFu, ar, o);
            az += __shfl_xor_sync(0xFFFFFFFFu, az, o);
            an += __shfl_xor_sync(0xFFFFFFFFu, an, o);
        }

        // ---- gate math + publish (lane 0 of each warp) ----
        if (lane == 0) {
            float er = __expf(-(gr_c + ar));
            float r  = __fdividef(1.f, 1.f + er);
            float ez = __expf(-(gz_c + az));
            float z  = __fdividef(1.f, 1.f + ez);
            float nx = gn_c + r * (an + bhn_c);
            float en = __expf(-2.f * nx);
            float n  = __fdividef(1.f - en, 1.f + en);      // tanh(nx)
            float hnew = n + z * (h_prev - n);
            g_h[(size_t)t * D_DIM + col] = hnew;
            h_prev = hnew;
            gr_c = grn; gz_c = gzn; gn_c = gnn;
        }
        __syncthreads();                   // all 8 column stores done (CTA HB)

        // release-atomic: bar above gives CTA-wide happens-before, release
        // publishes all 8 warps' h stores to the consumer's ld.acquire.
        if (tid == 0) atom_add_release(&g_cnt[t * CSTRIDE], 1u);
    }
}

// ---------------- launcher --------------------------------------------------
extern "C" void kernel_launch(void* const* d_in, const int* in_sizes, int n_in,
                              void* d_out, int out_size)
{
    const float* xs        = (const float*)d_in[0];
    const float* init_st   = (const float*)d_in[1];
    const float* Wir       = (const float*)d_in[2];
    const float* Wiz       = (const float*)d_in[3];
    const float* Win       = (const float*)d_in[4];
    const float* bir       = (const float*)d_in[5];
    const float* biz       = (const float*)d_in[6];
    const float* bin_      = (const float*)d_in[7];
    const float* Whr       = (const float*)d_in[8];
    const float* Whz       = (const float*)d_in[9];
    const float* Whn       = (const float*)d_in[10];
    const float* bhn       = (const float*)d_in[11];
    const float* Wl        = (const float*)d_in[12];
    const float* bl        = (const float*)d_in[13];
    const float* ln_scale  = (const float*)d_in[14];
    const float* ln_bias   = (const float*)d_in[15];
    float* out = (float*)d_out;

    // 1) clear counters (graph-replay determinism)
    clear_cnt_kernel<<<(T_LEN + 255) / 256, 256>>>();

    // 2) fully fused: recurrence + gates GEMM + post GEMM + layernorm
    fused_gru_kernel<<<NCTA + GATE_CTAS + POST_CTAS + LN_CTAS, 256>>>(
        xs, Wir, Wiz, Win, bir, biz, bin_, Whr, Whz, Whn, bhn, init_st,
        Wl, bl, ln_scale, ln_bias, out);
}